// round 5
// baseline (speedup 1.0000x reference)
#include <cuda_runtime.h>
#include <cuda_bf16.h>

// RUDY congestion map via 2D difference-array + summed-area reconstruction.
//
// H and V diff maps are INTERLEAVED as float2 at (x*DPITCH+y)*2 so that:
//   - scatter's per-position H/V atomic pair hits one 32B sector
//   - row_scan handles both maps in one coalesced pass
//   - col_scan loads float4 = {H,V} x 2 columns per thread (16B/sector useful)
// Pipeline: zero -> scatter (<=16 float2 positions per net, mixed 2D diff)
//           -> row_scan (inclusive scan along y per x-row)
//           -> col_scan (parallel scan along x per y-column) + max(|h|,|v|).

#define NBX 512
#define NBY 512
#define DPITCH 516          // row pitch (cols 0..512 used); mult of 4 for float4
#define DROWS  513          // rows 0..512 used

__device__ float g_diff[DROWS * DPITCH * 2];   // interleaved H,V

__device__ __forceinline__ float edge(int i, float bs) {
    return (float)i * bs;   // bs = 1000/512 = 125/64 exact; i*bs exact here
}

// overlap of [vmin, vmax] with bin i, clipped to [0, bs] — identical formula
// to the reference's clip(min(vmax, e[i+1]) - max(vmin, e[i]), 0, bs).
__device__ __forceinline__ float fval(float vmin, float vmax, int i, float bs) {
    float lo_e = edge(i, bs);
    float hi_e = edge(i + 1, bs);
    float ov = fminf(vmax, hi_e) - fmaxf(vmin, lo_e);
    return fminf(fmaxf(ov, 0.0f), bs);
}

// exact bin index of v (0..nb-1), correcting fp error in the division against
// the exactly-representable edges.
__device__ __forceinline__ int bin_of(float v, float inv_bs, float bs, int nb) {
    int i = (int)(v * inv_bs);
    if (i > nb - 1) i = nb - 1;
    if (i < 0) i = 0;
    if (i > 0 && v < edge(i, bs)) --i;
    else if (i < nb - 1 && v >= edge(i + 1, bs)) ++i;
    return i;
}

__global__ void zero_diff_kernel() {
    int total = DROWS * DPITCH * 2 / 4;
    float4* p = reinterpret_cast<float4*>(g_diff);
    for (int i = blockIdx.x * blockDim.x + threadIdx.x; i < total;
         i += gridDim.x * blockDim.x) {
        p[i] = make_float4(0.f, 0.f, 0.f, 0.f);
    }
}

__global__ void scatter_kernel(const float* __restrict__ pin_pos,
                               const float* __restrict__ net_weights,
                               const int* __restrict__ netpin_start,
                               const int* __restrict__ flat_netpin,
                               int num_nets, int P) {
    const float BSX = 1.953125f;          // 1000/512, exact
    const float BSY = 1.953125f;
    const float INV_BSX = 1.0f / 1.953125f;
    const float INV_BSY = 1.0f / 1.953125f;
    const float SCALE = 262144.0f / 100000.0f;  // 1/(BSX*BSY*0.1)

    for (int n = blockIdx.x * blockDim.x + threadIdx.x; n < num_nets;
         n += gridDim.x * blockDim.x) {
        int s = netpin_start[n];
        int e = netpin_start[n + 1];

        float xmin = 3.0e38f, xmax = -3.0e38f, ymin = 3.0e38f, ymax = -3.0e38f;
        for (int p = s; p < e; ++p) {
            int idx = __ldg(&flat_netpin[p]);
            float x = __ldg(&pin_pos[idx]);
            float y = __ldg(&pin_pos[P + idx]);
            xmin = fminf(xmin, x); xmax = fmaxf(xmax, x);
            ymin = fminf(ymin, y); ymax = fmaxf(ymax, y);
        }

        float sx = xmax - xmin;
        float sy = ymax - ymin;
        // zero span in either dim zeroes the ox*oy product for BOTH maps
        if (!(sx > 0.0f) || !(sy > 0.0f)) continue;

        float wt = net_weights[n] * SCALE;
        float wh = wt / sy;   // horizontal demand weight
        float wv = wt / sx;   // vertical demand weight

        int lox = bin_of(xmin, INV_BSX, BSX, NBX);
        int hix = bin_of(xmax, INV_BSX, BSX, NBX);
        int loy = bin_of(ymin, INV_BSY, BSY, NBY);
        int hiy = bin_of(ymax, INV_BSY, BSY, NBY);

        // unique difference positions along x: subset of {lo, lo+1, hi, hi+1}
        int pxs[4]; float dxs[4]; int mx = 0;
        pxs[mx++] = lox;
        pxs[mx++] = lox + 1;
        if (hix > lox + 1) pxs[mx++] = hix;
        if (hix + 1 > lox + 1) pxs[mx++] = hix + 1;
#pragma unroll
        for (int i = 0; i < 4; ++i) {
            if (i < mx)
                dxs[i] = fval(xmin, xmax, pxs[i], BSX)
                       - fval(xmin, xmax, pxs[i] - 1, BSX);
        }

        int pys[4]; float dys[4]; int my = 0;
        pys[my++] = loy;
        pys[my++] = loy + 1;
        if (hiy > loy + 1) pys[my++] = hiy;
        if (hiy + 1 > loy + 1) pys[my++] = hiy + 1;
#pragma unroll
        for (int j = 0; j < 4; ++j) {
            if (j < my)
                dys[j] = fval(ymin, ymax, pys[j], BSY)
                       - fval(ymin, ymax, pys[j] - 1, BSY);
        }

#pragma unroll
        for (int i = 0; i < 4; ++i) {
            if (i >= mx) break;
#pragma unroll
            for (int j = 0; j < 4; ++j) {
                if (j >= my) break;
                float v = dxs[i] * dys[j];
                int off = (pxs[i] * DPITCH + pys[j]) * 2;
                atomicAdd(&g_diff[off],     wh * v);
                atomicAdd(&g_diff[off + 1], wv * v);
            }
        }
    }
}

// inclusive scan along y (contiguous dim) for rows 0..511, both maps at once.
__global__ void row_scan_kernel() {
    __shared__ float wsH[16];
    __shared__ float wsV[16];
    int row = blockIdx.x;
    int t = threadIdx.x;
    int lane = t & 31, wid = t >> 5;

    float2* D = reinterpret_cast<float2*>(g_diff) + row * DPITCH;
    float2 hv = D[t];
    float h = hv.x, v = hv.y;
#pragma unroll
    for (int o = 1; o < 32; o <<= 1) {
        float nh = __shfl_up_sync(0xffffffff, h, o);
        float nv = __shfl_up_sync(0xffffffff, v, o);
        if (lane >= o) { h += nh; v += nv; }
    }
    if (lane == 31) { wsH[wid] = h; wsV[wid] = v; }
    __syncthreads();
    if (wid == 0) {
        float sv = (lane < 16) ? wsH[lane] : wsV[lane - 16];
#pragma unroll
        for (int o = 1; o < 16; o <<= 1) {
            float nv = __shfl_up_sync(0xffffffff, sv, o, 16);
            if ((lane & 15) >= o) sv += nv;
        }
        if (lane < 16) wsH[lane] = sv; else wsV[lane - 16] = sv;
    }
    __syncthreads();
    if (wid > 0) { h += wsH[wid - 1]; v += wsV[wid - 1]; }
    D[t] = make_float2(h, v);
}

// parallel inclusive scan along x for TWO y-columns per block (float4 load =
// {H,V} x 2 columns), then finalize out = max(|h|,|v|).  256 blocks x 512 thr.
__global__ void col_scan_finalize_kernel(float* __restrict__ out) {
    __shared__ float ws[4][16];
    int y0 = blockIdx.x * 2;     // first of two columns
    int t = threadIdx.x;         // x index
    int lane = t & 31, wid = t >> 5;

    // element index (t*DPITCH + y0)*2 is a multiple of 4 -> 16B aligned
    float4 q = *reinterpret_cast<const float4*>(&g_diff[(t * DPITCH + y0) * 2]);
    float s0 = q.x, s1 = q.y, s2 = q.z, s3 = q.w;   // H(y0),V(y0),H(y1),V(y1)

#pragma unroll
    for (int o = 1; o < 32; o <<= 1) {
        float n0 = __shfl_up_sync(0xffffffff, s0, o);
        float n1 = __shfl_up_sync(0xffffffff, s1, o);
        float n2 = __shfl_up_sync(0xffffffff, s2, o);
        float n3 = __shfl_up_sync(0xffffffff, s3, o);
        if (lane >= o) { s0 += n0; s1 += n1; s2 += n2; s3 += n3; }
    }
    if (lane == 31) {
        ws[0][wid] = s0; ws[1][wid] = s1; ws[2][wid] = s2; ws[3][wid] = s3;
    }
    __syncthreads();

    // warps 0..3 each scan one 16-long warp-sum sequence (lanes 0..15 active)
    if (wid < 4 && lane < 16) {
        float sv = ws[wid][lane];
#pragma unroll
        for (int o = 1; o < 16; o <<= 1) {
            float nv = __shfl_up_sync(0x0000ffff, sv, o, 16);
            if (lane >= o) sv += nv;
        }
        ws[wid][lane] = sv;
    }
    __syncthreads();

    if (wid > 0) {
        s0 += ws[0][wid - 1]; s1 += ws[1][wid - 1];
        s2 += ws[2][wid - 1]; s3 += ws[3][wid - 1];
    }
    // out[x][y] row-major, 8B store (x*512 + y0 is even)
    *reinterpret_cast<float2*>(&out[t * NBY + y0]) =
        make_float2(fmaxf(fabsf(s0), fabsf(s1)), fmaxf(fabsf(s2), fabsf(s3)));
}

extern "C" void kernel_launch(void* const* d_in, const int* in_sizes, int n_in,
                              void* d_out, int out_size) {
    const float* pin_pos      = (const float*)d_in[0];
    const float* net_weights  = (const float*)d_in[1];
    const int*   netpin_start = (const int*)d_in[2];
    const int*   flat_netpin  = (const int*)d_in[3];
    float* out = (float*)d_out;

    int P = in_sizes[0] / 2;
    int num_nets = in_sizes[2] - 1;

    zero_diff_kernel<<<148, 256>>>();
    scatter_kernel<<<(num_nets + 127) / 128, 128>>>(
        pin_pos, net_weights, netpin_start, flat_netpin, num_nets, P);
    row_scan_kernel<<<NBX, NBY>>>();
    col_scan_finalize_kernel<<<NBY / 2, NBX>>>(out);
}

// round 6
// speedup vs baseline: 1.4615x; 1.4615x over previous
#include <cuda_runtime.h>
#include <cuda_bf16.h>

// RUDY congestion map via 2D difference-array + summed-area reconstruction.
//
// H and V diff maps are INTERLEAVED as float2 at (x*DPITCH+y)*2.
// Pipeline (3 launches, no zero pass):
//   scatter : <=16 positions per net (mixed 2D difference of the separable
//             overlap), ONE red.global.add.v2.f32 per position for {H,V}.
//             Positions at index 512 are skipped (dead for the 512-bin grid),
//             so only [0,512)^2 is ever touched.
//   row_scan: inclusive scan along y (contiguous) per x-row, both maps.
//   col_scan: parallel scan along x per y-column (4 columns/block-thread),
//             finalize out = max(|h|,|v|), then RESTORE ZEROS so the diff
//             array is pristine for the next graph replay.

#define NBX 512
#define NBY 512
#define DPITCH 516          // row pitch (cols 0..511 used); mult of 4 for float4
#define DROWS  513          // allocated; only rows 0..511 touched now

__device__ float g_diff[DROWS * DPITCH * 2];   // interleaved H,V (zero-init)

__device__ __forceinline__ float edge(int i, float bs) {
    return (float)i * bs;   // bs = 1000/512 = 125/64 exact; i*bs exact here
}

// overlap of [vmin, vmax] with bin i, clipped to [0, bs] — identical formula
// to the reference's clip(min(vmax, e[i+1]) - max(vmin, e[i]), 0, bs).
__device__ __forceinline__ float fval(float vmin, float vmax, int i, float bs) {
    float lo_e = edge(i, bs);
    float hi_e = edge(i + 1, bs);
    float ov = fminf(vmax, hi_e) - fmaxf(vmin, lo_e);
    return fminf(fmaxf(ov, 0.0f), bs);
}

// exact bin index of v (0..nb-1), correcting fp error in the division against
// the exactly-representable edges.
__device__ __forceinline__ int bin_of(float v, float inv_bs, float bs, int nb) {
    int i = (int)(v * inv_bs);
    if (i > nb - 1) i = nb - 1;
    if (i < 0) i = 0;
    if (i > 0 && v < edge(i, bs)) --i;
    else if (i < nb - 1 && v >= edge(i + 1, bs)) ++i;
    return i;
}

__device__ __forceinline__ void red_add_v2(float* p, float a, float b) {
    // one L2 reduction for the interleaved {H,V} pair (8B aligned)
    asm volatile("red.global.add.v2.f32 [%0], {%1, %2};"
                 :: "l"(p), "f"(a), "f"(b) : "memory");
}

__global__ void scatter_kernel(const float* __restrict__ pin_pos,
                               const float* __restrict__ net_weights,
                               const int* __restrict__ netpin_start,
                               const int* __restrict__ flat_netpin,
                               int num_nets, int P) {
    const float BSX = 1.953125f;          // 1000/512, exact
    const float BSY = 1.953125f;
    const float INV_BSX = 1.0f / 1.953125f;
    const float INV_BSY = 1.0f / 1.953125f;
    const float SCALE = 262144.0f / 100000.0f;  // 1/(BSX*BSY*0.1)

    for (int n = blockIdx.x * blockDim.x + threadIdx.x; n < num_nets;
         n += gridDim.x * blockDim.x) {
        int s = netpin_start[n];
        int e = netpin_start[n + 1];

        float xmin = 3.0e38f, xmax = -3.0e38f, ymin = 3.0e38f, ymax = -3.0e38f;
        for (int p = s; p < e; ++p) {
            int idx = __ldg(&flat_netpin[p]);
            float x = __ldg(&pin_pos[idx]);
            float y = __ldg(&pin_pos[P + idx]);
            xmin = fminf(xmin, x); xmax = fmaxf(xmax, x);
            ymin = fminf(ymin, y); ymax = fmaxf(ymax, y);
        }

        float sx = xmax - xmin;
        float sy = ymax - ymin;
        // zero span in either dim zeroes the ox*oy product for BOTH maps
        if (!(sx > 0.0f) || !(sy > 0.0f)) continue;

        float wt = net_weights[n] * SCALE;
        float wh = wt / sy;   // horizontal demand weight
        float wv = wt / sx;   // vertical demand weight

        int lox = bin_of(xmin, INV_BSX, BSX, NBX);
        int hix = bin_of(xmax, INV_BSX, BSX, NBX);
        int loy = bin_of(ymin, INV_BSY, BSY, NBY);
        int hiy = bin_of(ymax, INV_BSY, BSY, NBY);

        // unique difference positions along x: subset of {lo, lo+1, hi, hi+1}
        int pxs[4]; float dxs[4]; int mx = 0;
        pxs[mx++] = lox;
        pxs[mx++] = lox + 1;
        if (hix > lox + 1) pxs[mx++] = hix;
        if (hix + 1 > lox + 1) pxs[mx++] = hix + 1;
#pragma unroll
        for (int i = 0; i < 4; ++i) {
            if (i < mx)
                dxs[i] = fval(xmin, xmax, pxs[i], BSX)
                       - fval(xmin, xmax, pxs[i] - 1, BSX);
        }

        int pys[4]; float dys[4]; int my = 0;
        pys[my++] = loy;
        pys[my++] = loy + 1;
        if (hiy > loy + 1) pys[my++] = hiy;
        if (hiy + 1 > loy + 1) pys[my++] = hiy + 1;
#pragma unroll
        for (int j = 0; j < 4; ++j) {
            if (j < my)
                dys[j] = fval(ymin, ymax, pys[j], BSY)
                       - fval(ymin, ymax, pys[j] - 1, BSY);
        }

#pragma unroll
        for (int i = 0; i < 4; ++i) {
            if (i >= mx) break;
            if (pxs[i] >= NBX) continue;   // index-512 positions are dead
#pragma unroll
            for (int j = 0; j < 4; ++j) {
                if (j >= my) break;
                if (pys[j] >= NBY) continue;
                float v = dxs[i] * dys[j];
                int off = (pxs[i] * DPITCH + pys[j]) * 2;
                red_add_v2(&g_diff[off], wh * v, wv * v);
            }
        }
    }
}

// inclusive scan along y (contiguous dim) for rows 0..511, both maps at once.
__global__ void row_scan_kernel() {
    __shared__ float wsH[16];
    __shared__ float wsV[16];
    int row = blockIdx.x;
    int t = threadIdx.x;
    int lane = t & 31, wid = t >> 5;

    float2* D = reinterpret_cast<float2*>(g_diff) + row * DPITCH;
    float2 hv = D[t];
    float h = hv.x, v = hv.y;
#pragma unroll
    for (int o = 1; o < 32; o <<= 1) {
        float nh = __shfl_up_sync(0xffffffff, h, o);
        float nv = __shfl_up_sync(0xffffffff, v, o);
        if (lane >= o) { h += nh; v += nv; }
    }
    if (lane == 31) { wsH[wid] = h; wsV[wid] = v; }
    __syncthreads();
    if (wid == 0) {
        float sv = (lane < 16) ? wsH[lane] : wsV[lane - 16];
#pragma unroll
        for (int o = 1; o < 16; o <<= 1) {
            float nv = __shfl_up_sync(0xffffffff, sv, o, 16);
            if ((lane & 15) >= o) sv += nv;
        }
        if (lane < 16) wsH[lane] = sv; else wsV[lane - 16] = sv;
    }
    __syncthreads();
    if (wid > 0) { h += wsH[wid - 1]; v += wsV[wid - 1]; }
    D[t] = make_float2(h, v);
}

// parallel inclusive scan along x for FOUR y-columns per block (2x float4 =
// {H,V} x 4 columns per thread), finalize max(|h|,|v|), restore zeros.
// 128 blocks x 512 threads = single wave on 148 SMs.
__global__ void col_scan_finalize_kernel(float* __restrict__ out) {
    __shared__ float ws[8][16];
    int y0 = blockIdx.x * 4;     // first of four columns
    int t = threadIdx.x;         // x index
    int lane = t & 31, wid = t >> 5;

    float* base = &g_diff[(t * DPITCH + y0) * 2];   // 16B aligned
    float4 qa = *reinterpret_cast<const float4*>(base);
    float4 qb = *reinterpret_cast<const float4*>(base + 4);
    float s0 = qa.x, s1 = qa.y, s2 = qa.z, s3 = qa.w;  // H(y0),V(y0),H(y1),V(y1)
    float s4 = qb.x, s5 = qb.y, s6 = qb.z, s7 = qb.w;  // H(y2),V(y2),H(y3),V(y3)

#pragma unroll
    for (int o = 1; o < 32; o <<= 1) {
        float n0 = __shfl_up_sync(0xffffffff, s0, o);
        float n1 = __shfl_up_sync(0xffffffff, s1, o);
        float n2 = __shfl_up_sync(0xffffffff, s2, o);
        float n3 = __shfl_up_sync(0xffffffff, s3, o);
        float n4 = __shfl_up_sync(0xffffffff, s4, o);
        float n5 = __shfl_up_sync(0xffffffff, s5, o);
        float n6 = __shfl_up_sync(0xffffffff, s6, o);
        float n7 = __shfl_up_sync(0xffffffff, s7, o);
        if (lane >= o) {
            s0 += n0; s1 += n1; s2 += n2; s3 += n3;
            s4 += n4; s5 += n5; s6 += n6; s7 += n7;
        }
    }
    if (lane == 31) {
        ws[0][wid] = s0; ws[1][wid] = s1; ws[2][wid] = s2; ws[3][wid] = s3;
        ws[4][wid] = s4; ws[5][wid] = s5; ws[6][wid] = s6; ws[7][wid] = s7;
    }
    __syncthreads();

    // warps 0..7 each scan one 16-long warp-sum sequence (lanes 0..15 active)
    if (wid < 8 && lane < 16) {
        float sv = ws[wid][lane];
#pragma unroll
        for (int o = 1; o < 16; o <<= 1) {
            float nv = __shfl_up_sync(0x0000ffff, sv, o, 16);
            if (lane >= o) sv += nv;
        }
        ws[wid][lane] = sv;
    }
    __syncthreads();

    if (wid > 0) {
        s0 += ws[0][wid - 1]; s1 += ws[1][wid - 1];
        s2 += ws[2][wid - 1]; s3 += ws[3][wid - 1];
        s4 += ws[4][wid - 1]; s5 += ws[5][wid - 1];
        s6 += ws[6][wid - 1]; s7 += ws[7][wid - 1];
    }

    // restore zeros so the next kernel_launch call starts from a clean array
    float4 z = make_float4(0.f, 0.f, 0.f, 0.f);
    *reinterpret_cast<float4*>(base) = z;
    *reinterpret_cast<float4*>(base + 4) = z;

    // out[x][y] row-major; x*512 + y0 is a multiple of 4 -> float4 store
    *reinterpret_cast<float4*>(&out[t * NBY + y0]) =
        make_float4(fmaxf(fabsf(s0), fabsf(s1)), fmaxf(fabsf(s2), fabsf(s3)),
                    fmaxf(fabsf(s4), fabsf(s5)), fmaxf(fabsf(s6), fabsf(s7)));
}

extern "C" void kernel_launch(void* const* d_in, const int* in_sizes, int n_in,
                              void* d_out, int out_size) {
    const float* pin_pos      = (const float*)d_in[0];
    const float* net_weights  = (const float*)d_in[1];
    const int*   netpin_start = (const int*)d_in[2];
    const int*   flat_netpin  = (const int*)d_in[3];
    float* out = (float*)d_out;

    int P = in_sizes[0] / 2;
    int num_nets = in_sizes[2] - 1;

    scatter_kernel<<<(num_nets + 127) / 128, 128>>>(
        pin_pos, net_weights, netpin_start, flat_netpin, num_nets, P);
    row_scan_kernel<<<NBX, NBY>>>();
    col_scan_finalize_kernel<<<NBY / 4, NBX>>>(out);
}

// round 7
// speedup vs baseline: 1.4633x; 1.0012x over previous
#include <cuda_runtime.h>
#include <cuda_bf16.h>

// RUDY congestion map via 2D difference-array + summed-area reconstruction.
//
// H and V diff maps are INTERLEAVED as float2 at (x*DPITCH+y)*2.
// Pipeline (3 launches, no zero pass):
//   scatter : bbox per net (pins fully unrolled to 8 -> all gather loads in
//             flight at once), then <=16 positions (mixed 2D difference of the
//             separable overlap), ONE red.global.add.v2.f32 per position.
//             Index-512 positions skipped (dead), so only [0,512)^2 touched.
//   row_scan: inclusive scan along y (contiguous) per x-row, both maps.
//   col_scan: parallel scan along x per y-column (4 columns/block-thread),
//             finalize out = max(|h|,|v|), then RESTORE ZEROS so the diff
//             array is pristine for the next graph replay.

#define NBX 512
#define NBY 512
#define DPITCH 516          // row pitch (cols 0..511 used); mult of 4 for float4
#define DROWS  513          // allocated; only rows 0..511 touched

__device__ float g_diff[DROWS * DPITCH * 2];   // interleaved H,V (zero-init)

__device__ __forceinline__ float edge(int i, float bs) {
    return (float)i * bs;   // bs = 1000/512 = 125/64 exact; i*bs exact here
}

// overlap of [vmin, vmax] with bin i, clipped to [0, bs] — identical formula
// to the reference's clip(min(vmax, e[i+1]) - max(vmin, e[i]), 0, bs).
__device__ __forceinline__ float fval(float vmin, float vmax, int i, float bs) {
    float lo_e = edge(i, bs);
    float hi_e = edge(i + 1, bs);
    float ov = fminf(vmax, hi_e) - fmaxf(vmin, lo_e);
    return fminf(fmaxf(ov, 0.0f), bs);
}

// exact bin index of v (0..nb-1), correcting fp error in the division against
// the exactly-representable edges.
__device__ __forceinline__ int bin_of(float v, float inv_bs, float bs, int nb) {
    int i = (int)(v * inv_bs);
    if (i > nb - 1) i = nb - 1;
    if (i < 0) i = 0;
    if (i > 0 && v < edge(i, bs)) --i;
    else if (i < nb - 1 && v >= edge(i + 1, bs)) ++i;
    return i;
}

__device__ __forceinline__ void red_add_v2(float* p, float a, float b) {
    // one L2 reduction for the interleaved {H,V} pair (8B aligned)
    asm volatile("red.global.add.v2.f32 [%0], {%1, %2};"
                 :: "l"(p), "f"(a), "f"(b) : "memory");
}

__global__ void scatter_kernel(const float* __restrict__ pin_pos,
                               const float* __restrict__ net_weights,
                               const int* __restrict__ netpin_start,
                               const int* __restrict__ flat_netpin,
                               int num_nets, int P) {
    const float BSX = 1.953125f;          // 1000/512, exact
    const float BSY = 1.953125f;
    const float INV_BSX = 1.0f / 1.953125f;
    const float INV_BSY = 1.0f / 1.953125f;
    const float SCALE = 262144.0f / 100000.0f;  // 1/(BSX*BSY*0.1)

    for (int n = blockIdx.x * blockDim.x + threadIdx.x; n < num_nets;
         n += gridDim.x * blockDim.x) {
        int s = netpin_start[n];
        int e = netpin_start[n + 1];
        int cnt = e - s;                    // dataset: 2..8

        // --- fully unrolled gather: all loads independent, MLP ~16 ---
        int idx[8];
#pragma unroll
        for (int k = 0; k < 8; ++k) {
            int p = s + ((k < cnt) ? k : 0);   // clamp: duplicate pin 0
            idx[k] = __ldg(&flat_netpin[p]);
        }
        float xv[8], yv[8];
#pragma unroll
        for (int k = 0; k < 8; ++k) {
            xv[k] = __ldg(&pin_pos[idx[k]]);
            yv[k] = __ldg(&pin_pos[P + idx[k]]);
        }
        float xmin = xv[0], xmax = xv[0], ymin = yv[0], ymax = yv[0];
#pragma unroll
        for (int k = 1; k < 8; ++k) {
            xmin = fminf(xmin, xv[k]); xmax = fmaxf(xmax, xv[k]);
            ymin = fminf(ymin, yv[k]); ymax = fmaxf(ymax, yv[k]);
        }
        // generic fallback if a net ever has >8 pins
        for (int p = s + 8; p < e; ++p) {
            int id = __ldg(&flat_netpin[p]);
            float x = __ldg(&pin_pos[id]);
            float y = __ldg(&pin_pos[P + id]);
            xmin = fminf(xmin, x); xmax = fmaxf(xmax, x);
            ymin = fminf(ymin, y); ymax = fmaxf(ymax, y);
        }

        float sx = xmax - xmin;
        float sy = ymax - ymin;
        // zero span in either dim zeroes the ox*oy product for BOTH maps
        if (!(sx > 0.0f) || !(sy > 0.0f)) continue;

        float wt = net_weights[n] * SCALE;
        float wh = wt / sy;   // horizontal demand weight
        float wv = wt / sx;   // vertical demand weight

        int lox = bin_of(xmin, INV_BSX, BSX, NBX);
        int hix = bin_of(xmax, INV_BSX, BSX, NBX);
        int loy = bin_of(ymin, INV_BSY, BSY, NBY);
        int hiy = bin_of(ymax, INV_BSY, BSY, NBY);

        // unique difference positions along x: subset of {lo, lo+1, hi, hi+1}
        int pxs[4]; float dxs[4]; int mx = 0;
        pxs[mx++] = lox;
        pxs[mx++] = lox + 1;
        if (hix > lox + 1) pxs[mx++] = hix;
        if (hix + 1 > lox + 1) pxs[mx++] = hix + 1;
#pragma unroll
        for (int i = 0; i < 4; ++i) {
            if (i < mx)
                dxs[i] = fval(xmin, xmax, pxs[i], BSX)
                       - fval(xmin, xmax, pxs[i] - 1, BSX);
        }

        int pys[4]; float dys[4]; int my = 0;
        pys[my++] = loy;
        pys[my++] = loy + 1;
        if (hiy > loy + 1) pys[my++] = hiy;
        if (hiy + 1 > loy + 1) pys[my++] = hiy + 1;
#pragma unroll
        for (int j = 0; j < 4; ++j) {
            if (j < my)
                dys[j] = fval(ymin, ymax, pys[j], BSY)
                       - fval(ymin, ymax, pys[j] - 1, BSY);
        }

#pragma unroll
        for (int i = 0; i < 4; ++i) {
            if (i >= mx) break;
            if (pxs[i] >= NBX) continue;   // index-512 positions are dead
#pragma unroll
            for (int j = 0; j < 4; ++j) {
                if (j >= my) break;
                if (pys[j] >= NBY) continue;
                float v = dxs[i] * dys[j];
                int off = (pxs[i] * DPITCH + pys[j]) * 2;
                red_add_v2(&g_diff[off], wh * v, wv * v);
            }
        }
    }
}

// inclusive scan along y (contiguous dim) for rows 0..511, both maps at once.
__global__ void row_scan_kernel() {
    __shared__ float wsH[16];
    __shared__ float wsV[16];
    int row = blockIdx.x;
    int t = threadIdx.x;
    int lane = t & 31, wid = t >> 5;

    float2* D = reinterpret_cast<float2*>(g_diff) + row * DPITCH;
    float2 hv = D[t];
    float h = hv.x, v = hv.y;
#pragma unroll
    for (int o = 1; o < 32; o <<= 1) {
        float nh = __shfl_up_sync(0xffffffff, h, o);
        float nv = __shfl_up_sync(0xffffffff, v, o);
        if (lane >= o) { h += nh; v += nv; }
    }
    if (lane == 31) { wsH[wid] = h; wsV[wid] = v; }
    __syncthreads();
    if (wid == 0) {
        float sv = (lane < 16) ? wsH[lane] : wsV[lane - 16];
#pragma unroll
        for (int o = 1; o < 16; o <<= 1) {
            float nv = __shfl_up_sync(0xffffffff, sv, o, 16);
            if ((lane & 15) >= o) sv += nv;
        }
        if (lane < 16) wsH[lane] = sv; else wsV[lane - 16] = sv;
    }
    __syncthreads();
    if (wid > 0) { h += wsH[wid - 1]; v += wsV[wid - 1]; }
    D[t] = make_float2(h, v);
}

// parallel inclusive scan along x for FOUR y-columns per block (2x float4 =
// {H,V} x 4 columns per thread), finalize max(|h|,|v|), restore zeros.
// 128 blocks x 512 threads.
__global__ void col_scan_finalize_kernel(float* __restrict__ out) {
    __shared__ float ws[8][16];
    int y0 = blockIdx.x * 4;     // first of four columns
    int t = threadIdx.x;         // x index
    int lane = t & 31, wid = t >> 5;

    float* base = &g_diff[(t * DPITCH + y0) * 2];   // 16B aligned
    float4 qa = *reinterpret_cast<const float4*>(base);
    float4 qb = *reinterpret_cast<const float4*>(base + 4);
    float s0 = qa.x, s1 = qa.y, s2 = qa.z, s3 = qa.w;  // H(y0),V(y0),H(y1),V(y1)
    float s4 = qb.x, s5 = qb.y, s6 = qb.z, s7 = qb.w;  // H(y2),V(y2),H(y3),V(y3)

#pragma unroll
    for (int o = 1; o < 32; o <<= 1) {
        float n0 = __shfl_up_sync(0xffffffff, s0, o);
        float n1 = __shfl_up_sync(0xffffffff, s1, o);
        float n2 = __shfl_up_sync(0xffffffff, s2, o);
        float n3 = __shfl_up_sync(0xffffffff, s3, o);
        float n4 = __shfl_up_sync(0xffffffff, s4, o);
        float n5 = __shfl_up_sync(0xffffffff, s5, o);
        float n6 = __shfl_up_sync(0xffffffff, s6, o);
        float n7 = __shfl_up_sync(0xffffffff, s7, o);
        if (lane >= o) {
            s0 += n0; s1 += n1; s2 += n2; s3 += n3;
            s4 += n4; s5 += n5; s6 += n6; s7 += n7;
        }
    }
    if (lane == 31) {
        ws[0][wid] = s0; ws[1][wid] = s1; ws[2][wid] = s2; ws[3][wid] = s3;
        ws[4][wid] = s4; ws[5][wid] = s5; ws[6][wid] = s6; ws[7][wid] = s7;
    }
    __syncthreads();

    // warps 0..7 each scan one 16-long warp-sum sequence (lanes 0..15 active)
    if (wid < 8 && lane < 16) {
        float sv = ws[wid][lane];
#pragma unroll
        for (int o = 1; o < 16; o <<= 1) {
            float nv = __shfl_up_sync(0x0000ffff, sv, o, 16);
            if (lane >= o) sv += nv;
        }
        ws[wid][lane] = sv;
    }
    __syncthreads();

    if (wid > 0) {
        s0 += ws[0][wid - 1]; s1 += ws[1][wid - 1];
        s2 += ws[2][wid - 1]; s3 += ws[3][wid - 1];
        s4 += ws[4][wid - 1]; s5 += ws[5][wid - 1];
        s6 += ws[6][wid - 1]; s7 += ws[7][wid - 1];
    }

    // restore zeros so the next kernel_launch call starts from a clean array
    float4 z = make_float4(0.f, 0.f, 0.f, 0.f);
    *reinterpret_cast<float4*>(base) = z;
    *reinterpret_cast<float4*>(base + 4) = z;

    // out[x][y] row-major; x*512 + y0 is a multiple of 4 -> float4 store
    *reinterpret_cast<float4*>(&out[t * NBY + y0]) =
        make_float4(fmaxf(fabsf(s0), fabsf(s1)), fmaxf(fabsf(s2), fabsf(s3)),
                    fmaxf(fabsf(s4), fabsf(s5)), fmaxf(fabsf(s6), fabsf(s7)));
}

extern "C" void kernel_launch(void* const* d_in, const int* in_sizes, int n_in,
                              void* d_out, int out_size) {
    const float* pin_pos      = (const float*)d_in[0];
    const float* net_weights  = (const float*)d_in[1];
    const int*   netpin_start = (const int*)d_in[2];
    const int*   flat_netpin  = (const int*)d_in[3];
    float* out = (float*)d_out;

    int P = in_sizes[0] / 2;
    int num_nets = in_sizes[2] - 1;

    scatter_kernel<<<(num_nets + 127) / 128, 128>>>(
        pin_pos, net_weights, netpin_start, flat_netpin, num_nets, P);
    row_scan_kernel<<<NBX, NBY>>>();
    col_scan_finalize_kernel<<<NBY / 4, NBX>>>(out);
}

// round 8
// speedup vs baseline: 1.5510x; 1.0599x over previous
#include <cuda_runtime.h>
#include <cuda_bf16.h>

// RUDY congestion map via 2D difference-array + summed-area reconstruction.
//
// H and V diff maps are INTERLEAVED as float2 at (x*DPITCH+y)*2.
// Pipeline (3 launches, no zero pass):
//   scatter : FOUR lanes per net. Each lane gathers <=2 pins, quad butterfly
//             (shfl.xor 1,2) combines the bbox, lane sub owns x-breakpoint
//             sub and issues <=4 red.global.add.v2.f32 for {H,V}.
//             Index-512 positions skipped (dead), only [0,512)^2 touched.
//   row_scan: inclusive scan along y (contiguous) per x-row, both maps.
//   col_scan: parallel scan along x per y-column (4 columns/block-thread),
//             finalize out = max(|h|,|v|), then RESTORE ZEROS so the diff
//             array is pristine for the next graph replay.

#define NBX 512
#define NBY 512
#define DPITCH 516          // row pitch (cols 0..511 used); mult of 4 for float4
#define DROWS  513          // allocated; only rows 0..511 touched

__device__ float g_diff[DROWS * DPITCH * 2];   // interleaved H,V (zero-init)

__device__ __forceinline__ float edge(int i, float bs) {
    return (float)i * bs;   // bs = 1000/512 = 125/64 exact; i*bs exact here
}

// overlap of [vmin, vmax] with bin i, clipped to [0, bs] — identical formula
// to the reference's clip(min(vmax, e[i+1]) - max(vmin, e[i]), 0, bs).
__device__ __forceinline__ float fval(float vmin, float vmax, int i, float bs) {
    float lo_e = edge(i, bs);
    float hi_e = edge(i + 1, bs);
    float ov = fminf(vmax, hi_e) - fmaxf(vmin, lo_e);
    return fminf(fmaxf(ov, 0.0f), bs);
}

// exact bin index of v (0..nb-1), correcting fp error in the division against
// the exactly-representable edges.
__device__ __forceinline__ int bin_of(float v, float inv_bs, float bs, int nb) {
    int i = (int)(v * inv_bs);
    if (i > nb - 1) i = nb - 1;
    if (i < 0) i = 0;
    if (i > 0 && v < edge(i, bs)) --i;
    else if (i < nb - 1 && v >= edge(i + 1, bs)) ++i;
    return i;
}

__device__ __forceinline__ void red_add_v2(float* p, float a, float b) {
    // one L2 reduction for the interleaved {H,V} pair (8B aligned)
    asm volatile("red.global.add.v2.f32 [%0], {%1, %2};"
                 :: "l"(p), "f"(a), "f"(b) : "memory");
}

__global__ void scatter_kernel(const float* __restrict__ pin_pos,
                               const float* __restrict__ net_weights,
                               const int* __restrict__ netpin_start,
                               const int* __restrict__ flat_netpin,
                               int num_nets, int P) {
    const float BSX = 1.953125f;          // 1000/512, exact
    const float BSY = 1.953125f;
    const float INV_BSX = 1.0f / 1.953125f;
    const float INV_BSY = 1.0f / 1.953125f;
    const float SCALE = 262144.0f / 100000.0f;  // 1/(BSX*BSY*0.1)

    int gt = blockIdx.x * blockDim.x + threadIdx.x;
    int n = gt >> 2;          // one net per quad of lanes
    int sub = gt & 3;
    bool valid = (n < num_nets);

    float xmin = 3.0e38f, xmax = -3.0e38f, ymin = 3.0e38f, ymax = -3.0e38f;
    int s = 0, cnt = 0;
    if (valid) {
        s = netpin_start[n];
        cnt = netpin_start[n + 1] - s;
    }

    // lane sub gathers pins sub, sub+4 (covers cnt<=8), fallback for more
    if (sub < cnt) {
        int id = __ldg(&flat_netpin[s + sub]);
        float x = __ldg(&pin_pos[id]);
        float y = __ldg(&pin_pos[P + id]);
        xmin = fminf(xmin, x); xmax = fmaxf(xmax, x);
        ymin = fminf(ymin, y); ymax = fmaxf(ymax, y);
    }
    if (sub + 4 < cnt) {
        int id = __ldg(&flat_netpin[s + sub + 4]);
        float x = __ldg(&pin_pos[id]);
        float y = __ldg(&pin_pos[P + id]);
        xmin = fminf(xmin, x); xmax = fmaxf(xmax, x);
        ymin = fminf(ymin, y); ymax = fmaxf(ymax, y);
    }
    for (int k = sub + 8; k < cnt; k += 4) {
        int id = __ldg(&flat_netpin[s + k]);
        float x = __ldg(&pin_pos[id]);
        float y = __ldg(&pin_pos[P + id]);
        xmin = fminf(xmin, x); xmax = fmaxf(xmax, x);
        ymin = fminf(ymin, y); ymax = fmaxf(ymax, y);
    }

    // quad butterfly: combine bbox across the 4 lanes (xor 1, then 2).
    // Whole warp executes these (no early returns above), so full mask is safe;
    // quads are 4 consecutive lanes, so valid/invalid quads never mix.
#pragma unroll
    for (int o = 1; o <= 2; o <<= 1) {
        xmin = fminf(xmin, __shfl_xor_sync(0xffffffff, xmin, o));
        xmax = fmaxf(xmax, __shfl_xor_sync(0xffffffff, xmax, o));
        ymin = fminf(ymin, __shfl_xor_sync(0xffffffff, ymin, o));
        ymax = fmaxf(ymax, __shfl_xor_sync(0xffffffff, ymax, o));
    }

    if (!valid) return;

    float sx = xmax - xmin;
    float sy = ymax - ymin;
    // zero span in either dim zeroes the ox*oy product for BOTH maps
    if (!(sx > 0.0f) || !(sy > 0.0f)) return;

    float wt = __ldg(&net_weights[n]) * SCALE;
    float wh = wt / sy;   // horizontal demand weight
    float wv = wt / sx;   // vertical demand weight

    int lox = bin_of(xmin, INV_BSX, BSX, NBX);
    int hix = bin_of(xmax, INV_BSX, BSX, NBX);
    int loy = bin_of(ymin, INV_BSY, BSY, NBY);
    int hiy = bin_of(ymax, INV_BSY, BSY, NBY);

    // lane sub owns x-breakpoint sub: {lox, lox+1, hix, hix+1} with dedup.
    int px = (sub < 2) ? (lox + sub) : (hix + (sub - 2));
    bool xok = (sub < 2) || (sub == 2 ? (hix > lox + 1) : (hix > lox));
    if (!xok || px >= NBX) return;     // index-512 positions are dead

    float dx = fval(xmin, xmax, px, BSX) - fval(xmin, xmax, px - 1, BSX);
    float ah = wh * dx;
    float av = wv * dx;
    float* rowp = &g_diff[px * DPITCH * 2];

#pragma unroll
    for (int j = 0; j < 4; ++j) {
        int py = (j < 2) ? (loy + j) : (hiy + (j - 2));
        bool yok = (j < 2) || (j == 2 ? (hiy > loy + 1) : (hiy > loy));
        if (!yok || py >= NBY) continue;
        float dy = fval(ymin, ymax, py, BSY) - fval(ymin, ymax, py - 1, BSY);
        red_add_v2(rowp + py * 2, ah * dy, av * dy);
    }
}

// inclusive scan along y (contiguous dim) for rows 0..511, both maps at once.
__global__ void row_scan_kernel() {
    __shared__ float wsH[16];
    __shared__ float wsV[16];
    int row = blockIdx.x;
    int t = threadIdx.x;
    int lane = t & 31, wid = t >> 5;

    float2* D = reinterpret_cast<float2*>(g_diff) + row * DPITCH;
    float2 hv = D[t];
    float h = hv.x, v = hv.y;
#pragma unroll
    for (int o = 1; o < 32; o <<= 1) {
        float nh = __shfl_up_sync(0xffffffff, h, o);
        float nv = __shfl_up_sync(0xffffffff, v, o);
        if (lane >= o) { h += nh; v += nv; }
    }
    if (lane == 31) { wsH[wid] = h; wsV[wid] = v; }
    __syncthreads();
    if (wid == 0) {
        float sv = (lane < 16) ? wsH[lane] : wsV[lane - 16];
#pragma unroll
        for (int o = 1; o < 16; o <<= 1) {
            float nv = __shfl_up_sync(0xffffffff, sv, o, 16);
            if ((lane & 15) >= o) sv += nv;
        }
        if (lane < 16) wsH[lane] = sv; else wsV[lane - 16] = sv;
    }
    __syncthreads();
    if (wid > 0) { h += wsH[wid - 1]; v += wsV[wid - 1]; }
    D[t] = make_float2(h, v);
}

// parallel inclusive scan along x for FOUR y-columns per block (2x float4 =
// {H,V} x 4 columns per thread), finalize max(|h|,|v|), restore zeros.
// 128 blocks x 512 threads.
__global__ void col_scan_finalize_kernel(float* __restrict__ out) {
    __shared__ float ws[8][16];
    int y0 = blockIdx.x * 4;     // first of four columns
    int t = threadIdx.x;         // x index
    int lane = t & 31, wid = t >> 5;

    float* base = &g_diff[(t * DPITCH + y0) * 2];   // 16B aligned
    float4 qa = *reinterpret_cast<const float4*>(base);
    float4 qb = *reinterpret_cast<const float4*>(base + 4);
    float s0 = qa.x, s1 = qa.y, s2 = qa.z, s3 = qa.w;  // H(y0),V(y0),H(y1),V(y1)
    float s4 = qb.x, s5 = qb.y, s6 = qb.z, s7 = qb.w;  // H(y2),V(y2),H(y3),V(y3)

#pragma unroll
    for (int o = 1; o < 32; o <<= 1) {
        float n0 = __shfl_up_sync(0xffffffff, s0, o);
        float n1 = __shfl_up_sync(0xffffffff, s1, o);
        float n2 = __shfl_up_sync(0xffffffff, s2, o);
        float n3 = __shfl_up_sync(0xffffffff, s3, o);
        float n4 = __shfl_up_sync(0xffffffff, s4, o);
        float n5 = __shfl_up_sync(0xffffffff, s5, o);
        float n6 = __shfl_up_sync(0xffffffff, s6, o);
        float n7 = __shfl_up_sync(0xffffffff, s7, o);
        if (lane >= o) {
            s0 += n0; s1 += n1; s2 += n2; s3 += n3;
            s4 += n4; s5 += n5; s6 += n6; s7 += n7;
        }
    }
    if (lane == 31) {
        ws[0][wid] = s0; ws[1][wid] = s1; ws[2][wid] = s2; ws[3][wid] = s3;
        ws[4][wid] = s4; ws[5][wid] = s5; ws[6][wid] = s6; ws[7][wid] = s7;
    }
    __syncthreads();

    // warps 0..7 each scan one 16-long warp-sum sequence (lanes 0..15 active)
    if (wid < 8 && lane < 16) {
        float sv = ws[wid][lane];
#pragma unroll
        for (int o = 1; o < 16; o <<= 1) {
            float nv = __shfl_up_sync(0x0000ffff, sv, o, 16);
            if (lane >= o) sv += nv;
        }
        ws[wid][lane] = sv;
    }
    __syncthreads();

    if (wid > 0) {
        s0 += ws[0][wid - 1]; s1 += ws[1][wid - 1];
        s2 += ws[2][wid - 1]; s3 += ws[3][wid - 1];
        s4 += ws[4][wid - 1]; s5 += ws[5][wid - 1];
        s6 += ws[6][wid - 1]; s7 += ws[7][wid - 1];
    }

    // restore zeros so the next kernel_launch call starts from a clean array
    float4 z = make_float4(0.f, 0.f, 0.f, 0.f);
    *reinterpret_cast<float4*>(base) = z;
    *reinterpret_cast<float4*>(base + 4) = z;

    // out[x][y] row-major; x*512 + y0 is a multiple of 4 -> float4 store
    *reinterpret_cast<float4*>(&out[t * NBY + y0]) =
        make_float4(fmaxf(fabsf(s0), fabsf(s1)), fmaxf(fabsf(s2), fabsf(s3)),
                    fmaxf(fabsf(s4), fabsf(s5)), fmaxf(fabsf(s6), fabsf(s7)));
}

extern "C" void kernel_launch(void* const* d_in, const int* in_sizes, int n_in,
                              void* d_out, int out_size) {
    const float* pin_pos      = (const float*)d_in[0];
    const float* net_weights  = (const float*)d_in[1];
    const int*   netpin_start = (const int*)d_in[2];
    const int*   flat_netpin  = (const int*)d_in[3];
    float* out = (float*)d_out;

    int P = in_sizes[0] / 2;
    int num_nets = in_sizes[2] - 1;

    int threads = num_nets * 4;
    scatter_kernel<<<(threads + 255) / 256, 256>>>(
        pin_pos, net_weights, netpin_start, flat_netpin, num_nets, P);
    row_scan_kernel<<<NBX, NBY>>>();
    col_scan_finalize_kernel<<<NBY / 4, NBX>>>(out);
}